// round 3
// baseline (speedup 1.0000x reference)
#include <cuda_runtime.h>
#include <cstdint>
#include <cstddef>

// Problem dims (fixed by the dataset)
#define D_DIM 1024
#define M_TOT 32768            // B*S = 32*1024
#define N_TOT 3072             // 3*D
#define K_TOT 1024             // D
#define RANK  5

// GEMM tiling
#define BM 128
#define BN 128
#define BK 32
#define STRIDE 36              // smem row stride in floats (pad 32 -> 36, conflict-free)
#define ASZ (BM * STRIDE)      // floats per (matrix, stage)
#define SMEM_BYTES (4 * ASZ * 4)  // 2 stages * (A + B) * 4B = 73728

// Effective weight W + delta, computed once per launch. 12 MB device global.
__device__ float g_Wd[(size_t)N_TOT * K_TOT];

// ---------------------------------------------------------------------------
// Prep: Wd[n][k] = W[n][k] + (LoRA delta on rows [D, 3D))
// ---------------------------------------------------------------------------
__global__ void prep_wd(const float* __restrict__ W,
                        const float* __restrict__ A0, const float* __restrict__ A1,
                        const float* __restrict__ B0, const float* __restrict__ B1,
                        const float* __restrict__ s0p, const float* __restrict__ s1p)
{
    int idx = blockIdx.x * blockDim.x + threadIdx.x;
    if (idx >= N_TOT * K_TOT) return;
    int n = idx / K_TOT;
    int k = idx - n * K_TOT;
    float w = W[idx];
    if (n >= D_DIM) {
        if (n < 2 * D_DIM) {
            int r = n - D_DIM;
            float acc = 0.f;
#pragma unroll
            for (int j = 0; j < RANK; j++)
                acc += B0[r * RANK + j] * A0[j * K_TOT + k];
            w += s0p[0] * acc;
        } else {
            int r = n - 2 * D_DIM;
            float acc = 0.f;
#pragma unroll
            for (int j = 0; j < RANK; j++)
                acc += B1[r * RANK + j] * A1[j * K_TOT + k];
            w += s1p[0] * acc;
        }
    }
    g_Wd[idx] = w;
}

// ---------------------------------------------------------------------------
// TF32 GEMM: C[M,N] = A[M,K] * Wd[N,K]^T + bias
// ---------------------------------------------------------------------------
__device__ __forceinline__ uint32_t f2tf32(float x) {
    uint32_t r;
    asm("cvt.rna.tf32.f32 %0, %1;" : "=r"(r) : "f"(x));
    return r;
}

__global__ __launch_bounds__(256, 1)
void gemm_tf32(const float* __restrict__ A,
               const float* __restrict__ bias,
               float* __restrict__ C)
{
    extern __shared__ float smem[];
    float* As = smem;               // 2 stages * ASZ
    float* Bs = smem + 2 * ASZ;     // 2 stages * ASZ

    const int tid  = threadIdx.x;
    const int warp = tid >> 5;
    const int lane = tid & 31;
    const int wm = warp >> 2;       // 0..1  (64-row band)
    const int wn = warp & 3;        // 0..3  (32-col band)
    const int qr = lane >> 2;       // 0..7
    const int qc = lane & 3;        // 0..3

    const int m0 = blockIdx.y * BM;
    const int n0 = blockIdx.x * BN;

    // cp.async producer mapping: 16B per thread, 8 threads per 32-float row
    const int lrow = tid >> 3;              // 0..31
    const int lcol = (tid & 7) << 2;        // float offset in row

    const float* gA = A    + (size_t)(m0 + lrow) * K_TOT + lcol;
    const float* gB = g_Wd + (size_t)(n0 + lrow) * K_TOT + lcol;

    const uint32_t sA0 = (uint32_t)__cvta_generic_to_shared(&As[lrow * STRIDE + lcol]);
    const uint32_t sB0 = (uint32_t)__cvta_generic_to_shared(&Bs[lrow * STRIDE + lcol]);

    float acc[4][4][4];
#pragma unroll
    for (int i = 0; i < 4; i++)
#pragma unroll
        for (int j = 0; j < 4; j++)
#pragma unroll
            for (int c = 0; c < 4; c++) acc[i][j][c] = 0.f;

    auto load_stage = [&](int s, int kt) {
        const int k0 = kt * BK;
        const uint32_t sbase_a = sA0 + (uint32_t)(s * ASZ * 4);
        const uint32_t sbase_b = sB0 + (uint32_t)(s * ASZ * 4);
#pragma unroll
        for (int i = 0; i < 4; i++) {
            asm volatile("cp.async.cg.shared.global [%0], [%1], 16;"
                         :: "r"(sbase_a + (uint32_t)(i * 32 * STRIDE * 4)),
                            "l"(gA + (size_t)i * 32 * K_TOT + k0));
            asm volatile("cp.async.cg.shared.global [%0], [%1], 16;"
                         :: "r"(sbase_b + (uint32_t)(i * 32 * STRIDE * 4)),
                            "l"(gB + (size_t)i * 32 * K_TOT + k0));
        }
        asm volatile("cp.async.commit_group;");
    };

    constexpr int NT = K_TOT / BK;  // 32
    load_stage(0, 0);

    for (int kt = 0; kt < NT; kt++) {
        if (kt + 1 < NT) {
            load_stage((kt + 1) & 1, kt + 1);
            asm volatile("cp.async.wait_group 1;");
        } else {
            asm volatile("cp.async.wait_group 0;");
        }
        __syncthreads();

        const float* a_tile = &As[(kt & 1) * ASZ];
        const float* b_tile = &Bs[(kt & 1) * ASZ];

#pragma unroll
        for (int kk = 0; kk < BK / 8; kk++) {
            const int k8 = kk * 8;
            uint32_t af[4][4], bf[4][2];
#pragma unroll
            for (int mt = 0; mt < 4; mt++) {
                const int br = wm * 64 + mt * 16;
                af[mt][0] = f2tf32(a_tile[(br + qr)     * STRIDE + k8 + qc]);
                af[mt][1] = f2tf32(a_tile[(br + qr + 8) * STRIDE + k8 + qc]);
                af[mt][2] = f2tf32(a_tile[(br + qr)     * STRIDE + k8 + qc + 4]);
                af[mt][3] = f2tf32(a_tile[(br + qr + 8) * STRIDE + k8 + qc + 4]);
            }
#pragma unroll
            for (int nt = 0; nt < 4; nt++) {
                const int bn = wn * 32 + nt * 8;
                bf[nt][0] = f2tf32(b_tile[(bn + qr) * STRIDE + k8 + qc]);
                bf[nt][1] = f2tf32(b_tile[(bn + qr) * STRIDE + k8 + qc + 4]);
            }
#pragma unroll
            for (int mt = 0; mt < 4; mt++)
#pragma unroll
                for (int nt = 0; nt < 4; nt++) {
                    asm volatile(
                        "mma.sync.aligned.m16n8k8.row.col.f32.tf32.tf32.f32 "
                        "{%0,%1,%2,%3},{%4,%5,%6,%7},{%8,%9},{%0,%1,%2,%3};"
                        : "+f"(acc[mt][nt][0]), "+f"(acc[mt][nt][1]),
                          "+f"(acc[mt][nt][2]), "+f"(acc[mt][nt][3])
                        : "r"(af[mt][0]), "r"(af[mt][1]), "r"(af[mt][2]), "r"(af[mt][3]),
                          "r"(bf[nt][0]), "r"(bf[nt][1]));
                }
        }
        __syncthreads();
    }

    // Epilogue: +bias, store fp32
#pragma unroll
    for (int mt = 0; mt < 4; mt++) {
        const int row0 = m0 + wm * 64 + mt * 16 + qr;
#pragma unroll
        for (int nt = 0; nt < 4; nt++) {
            const int col0 = n0 + wn * 32 + nt * 8 + qc * 2;
            const float b0v = bias[col0];
            const float b1v = bias[col0 + 1];
            C[(size_t)row0 * N_TOT + col0]           = acc[mt][nt][0] + b0v;
            C[(size_t)row0 * N_TOT + col0 + 1]       = acc[mt][nt][1] + b1v;
            C[(size_t)(row0 + 8) * N_TOT + col0]     = acc[mt][nt][2] + b0v;
            C[(size_t)(row0 + 8) * N_TOT + col0 + 1] = acc[mt][nt][3] + b1v;
        }
    }
}

// ---------------------------------------------------------------------------
extern "C" void kernel_launch(void* const* d_in, const int* in_sizes, int n_in,
                              void* d_out, int out_size)
{
    const float* x    = (const float*)d_in[0];
    const float* W    = (const float*)d_in[1];
    const float* bias = (const float*)d_in[2];
    const float* A0   = (const float*)d_in[3];
    const float* A1   = (const float*)d_in[4];
    const float* B0   = (const float*)d_in[5];
    const float* B1   = (const float*)d_in[6];
    const float* s0   = (const float*)d_in[7];
    const float* s1   = (const float*)d_in[8];
    float* out = (float*)d_out;

    (void)in_sizes; (void)n_in; (void)out_size;

    // 1) Materialize W + LoRA delta into the device-global weight buffer.
    prep_wd<<<(N_TOT * K_TOT + 255) / 256, 256>>>(W, A0, A1, B0, B1, s0, s1);

    // 2) TF32 tensor-core GEMM with fused bias.
    cudaFuncSetAttribute(gemm_tf32, cudaFuncAttributeMaxDynamicSharedMemorySize,
                         SMEM_BYTES);
    dim3 grid(N_TOT / BN, M_TOT / BM);   // x = N tiles (fast) for L2 reuse of A
    gemm_tf32<<<grid, 256, SMEM_BYTES>>>(x, bias, out);
}

// round 6
// speedup vs baseline: 1.0637x; 1.0637x over previous
#include <cuda_runtime.h>
#include <cstdint>
#include <cstddef>

// Problem dims (fixed by the dataset)
#define D_DIM 1024
#define M_TOT 32768            // B*S = 32*1024
#define N_TOT 3072             // 3*D
#define K_TOT 1024             // D
#define RANK  5

// GEMM tiling
#define BM 128
#define BN 128
#define BK 32
#define STRIDE 36              // smem row stride in floats (pad 32 -> 36, conflict-free)
#define ASZ (BM * STRIDE)      // floats per (matrix, stage)
#define SMEM_BYTES (4 * ASZ * 4)  // 2 stages * (A + B) * 4B = 73728

// Pre-rounded operands (tf32 RNA applied ahead of time; GEMM loads raw bits).
__device__ float g_Wd[(size_t)N_TOT * K_TOT];   // W + LoRA delta, rounded
__device__ float g_xr[(size_t)M_TOT * K_TOT];   // x, rounded

__device__ __forceinline__ uint32_t f2tf32(float x) {
    uint32_t r;
    asm("cvt.rna.tf32.f32 %0, %1;" : "=r"(r) : "f"(x));
    return r;
}

// ---------------------------------------------------------------------------
// Prep: Wd[n][k] = round_tf32( W[n][k] + LoRA delta on rows [D, 3D) )
// ---------------------------------------------------------------------------
__global__ void prep_wd(const float* __restrict__ W,
                        const float* __restrict__ A0, const float* __restrict__ A1,
                        const float* __restrict__ B0, const float* __restrict__ B1,
                        const float* __restrict__ s0p, const float* __restrict__ s1p)
{
    int idx = blockIdx.x * blockDim.x + threadIdx.x;
    if (idx >= N_TOT * K_TOT) return;
    int n = idx / K_TOT;
    int k = idx - n * K_TOT;
    float w = W[idx];
    if (n >= D_DIM) {
        if (n < 2 * D_DIM) {
            int r = n - D_DIM;
            float acc = 0.f;
#pragma unroll
            for (int j = 0; j < RANK; j++)
                acc += B0[r * RANK + j] * A0[j * K_TOT + k];
            w += s0p[0] * acc;
        } else {
            int r = n - 2 * D_DIM;
            float acc = 0.f;
#pragma unroll
            for (int j = 0; j < RANK; j++)
                acc += B1[r * RANK + j] * A1[j * K_TOT + k];
            w += s1p[0] * acc;
        }
    }
    g_Wd[idx] = __uint_as_float(f2tf32(w));
}

__global__ void prep_xr(const float4* __restrict__ x)
{
    size_t i = (size_t)blockIdx.x * blockDim.x + threadIdx.x;   // 8M float4s
    float4 v = x[i];
    v.x = __uint_as_float(f2tf32(v.x));
    v.y = __uint_as_float(f2tf32(v.y));
    v.z = __uint_as_float(f2tf32(v.z));
    v.w = __uint_as_float(f2tf32(v.w));
    reinterpret_cast<float4*>(g_xr)[i] = v;
}

// ---------------------------------------------------------------------------
// TF32 GEMM: C[M,N] = A[M,K] * Wd[N,K]^T + bias   (operands pre-rounded)
// ---------------------------------------------------------------------------
__global__ __launch_bounds__(256, 2)
void gemm_tf32(const float* __restrict__ bias,
               float* __restrict__ C)
{
    extern __shared__ float smem[];
    float* As = smem;               // 2 stages * ASZ
    float* Bs = smem + 2 * ASZ;     // 2 stages * ASZ

    const int tid  = threadIdx.x;
    const int warp = tid >> 5;
    const int lane = tid & 31;
    const int wm = warp >> 2;       // 0..1  (64-row band)
    const int wn = warp & 3;        // 0..3  (32-col band)
    const int qr = lane >> 2;       // 0..7
    const int qc = lane & 3;        // 0..3

    const int m0 = blockIdx.y * BM;
    const int n0 = blockIdx.x * BN;

    // cp.async producer mapping: 16B per thread, 8 threads per 32-float row
    const int lrow = tid >> 3;              // 0..31
    const int lcol = (tid & 7) << 2;        // float offset in row

    const float* gA = g_xr + (size_t)(m0 + lrow) * K_TOT + lcol;
    const float* gB = g_Wd + (size_t)(n0 + lrow) * K_TOT + lcol;

    const uint32_t sA0 = (uint32_t)__cvta_generic_to_shared(&As[lrow * STRIDE + lcol]);
    const uint32_t sB0 = (uint32_t)__cvta_generic_to_shared(&Bs[lrow * STRIDE + lcol]);

    float acc[4][4][4];
#pragma unroll
    for (int i = 0; i < 4; i++)
#pragma unroll
        for (int j = 0; j < 4; j++)
#pragma unroll
            for (int c = 0; c < 4; c++) acc[i][j][c] = 0.f;

    auto load_stage = [&](int s, int kt) {
        const int k0 = kt * BK;
        const uint32_t sbase_a = sA0 + (uint32_t)(s * ASZ * 4);
        const uint32_t sbase_b = sB0 + (uint32_t)(s * ASZ * 4);
#pragma unroll
        for (int i = 0; i < 4; i++) {
            asm volatile("cp.async.cg.shared.global [%0], [%1], 16;"
                         :: "r"(sbase_a + (uint32_t)(i * 32 * STRIDE * 4)),
                            "l"(gA + (size_t)i * 32 * K_TOT + k0));
            asm volatile("cp.async.cg.shared.global [%0], [%1], 16;"
                         :: "r"(sbase_b + (uint32_t)(i * 32 * STRIDE * 4)),
                            "l"(gB + (size_t)i * 32 * K_TOT + k0));
        }
        asm volatile("cp.async.commit_group;");
    };

    constexpr int NT = K_TOT / BK;  // 32
    load_stage(0, 0);

    for (int kt = 0; kt < NT; kt++) {
        if (kt + 1 < NT) {
            load_stage((kt + 1) & 1, kt + 1);
            asm volatile("cp.async.wait_group 1;");
        } else {
            asm volatile("cp.async.wait_group 0;");
        }
        __syncthreads();

        // Raw-bit fragment loads: operands are pre-rounded, no cvt needed.
        const uint32_t* a_tile = reinterpret_cast<const uint32_t*>(&As[(kt & 1) * ASZ]);
        const uint32_t* b_tile = reinterpret_cast<const uint32_t*>(&Bs[(kt & 1) * ASZ]);

#pragma unroll
        for (int kk = 0; kk < BK / 8; kk++) {
            const int k8 = kk * 8;
            uint32_t af[4][4], bf[4][2];
#pragma unroll
            for (int mt = 0; mt < 4; mt++) {
                const int br = wm * 64 + mt * 16;
                af[mt][0] = a_tile[(br + qr)     * STRIDE + k8 + qc];
                af[mt][1] = a_tile[(br + qr + 8) * STRIDE + k8 + qc];
                af[mt][2] = a_tile[(br + qr)     * STRIDE + k8 + qc + 4];
                af[mt][3] = a_tile[(br + qr + 8) * STRIDE + k8 + qc + 4];
            }
#pragma unroll
            for (int nt = 0; nt < 4; nt++) {
                const int bn = wn * 32 + nt * 8;
                bf[nt][0] = b_tile[(bn + qr) * STRIDE + k8 + qc];
                bf[nt][1] = b_tile[(bn + qr) * STRIDE + k8 + qc + 4];
            }
#pragma unroll
            for (int mt = 0; mt < 4; mt++)
#pragma unroll
                for (int nt = 0; nt < 4; nt++) {
                    asm volatile(
                        "mma.sync.aligned.m16n8k8.row.col.f32.tf32.tf32.f32 "
                        "{%0,%1,%2,%3},{%4,%5,%6,%7},{%8,%9},{%0,%1,%2,%3};"
                        : "+f"(acc[mt][nt][0]), "+f"(acc[mt][nt][1]),
                          "+f"(acc[mt][nt][2]), "+f"(acc[mt][nt][3])
                        : "r"(af[mt][0]), "r"(af[mt][1]), "r"(af[mt][2]), "r"(af[mt][3]),
                          "r"(bf[nt][0]), "r"(bf[nt][1]));
                }
        }
        __syncthreads();
    }

    // Epilogue: +bias, vectorized float2 stores
#pragma unroll
    for (int mt = 0; mt < 4; mt++) {
        const int row0 = m0 + wm * 64 + mt * 16 + qr;
#pragma unroll
        for (int nt = 0; nt < 4; nt++) {
            const int col0 = n0 + wn * 32 + nt * 8 + qc * 2;
            const float2 bv = *reinterpret_cast<const float2*>(&bias[col0]);
            float2 v0, v1;
            v0.x = acc[mt][nt][0] + bv.x;
            v0.y = acc[mt][nt][1] + bv.y;
            v1.x = acc[mt][nt][2] + bv.x;
            v1.y = acc[mt][nt][3] + bv.y;
            *reinterpret_cast<float2*>(&C[(size_t)row0 * N_TOT + col0])       = v0;
            *reinterpret_cast<float2*>(&C[(size_t)(row0 + 8) * N_TOT + col0]) = v1;
        }
    }
}

// ---------------------------------------------------------------------------
extern "C" void kernel_launch(void* const* d_in, const int* in_sizes, int n_in,
                              void* d_out, int out_size)
{
    const float* x    = (const float*)d_in[0];
    const float* W    = (const float*)d_in[1];
    const float* bias = (const float*)d_in[2];
    const float* A0   = (const float*)d_in[3];
    const float* A1   = (const float*)d_in[4];
    const float* B0   = (const float*)d_in[5];
    const float* B1   = (const float*)d_in[6];
    const float* s0   = (const float*)d_in[7];
    const float* s1   = (const float*)d_in[8];
    float* out = (float*)d_out;

    (void)in_sizes; (void)n_in; (void)out_size;

    // 1) Materialize rounded W + LoRA delta, and rounded x.
    prep_wd<<<(N_TOT * K_TOT + 255) / 256, 256>>>(W, A0, A1, B0, B1, s0, s1);
    prep_xr<<<(M_TOT * K_TOT / 4) / 256, 256>>>(reinterpret_cast<const float4*>(x));

    // 2) TF32 tensor-core GEMM with fused bias, 2 CTAs/SM.
    cudaFuncSetAttribute(gemm_tf32, cudaFuncAttributeMaxDynamicSharedMemorySize,
                         SMEM_BYTES);
    dim3 grid(N_TOT / BN, M_TOT / BM);   // x = N tiles (fast) for L2 reuse of A
    gemm_tf32<<<grid, 256, SMEM_BYTES>>>(bias, out);
}

// round 9
// speedup vs baseline: 1.3404x; 1.2601x over previous
#include <cuda_runtime.h>
#include <cstdint>
#include <cstddef>

// Problem dims (fixed by the dataset)
#define D_DIM 1024
#define M_TOT 32768            // B*S
#define N_TOT 3072             // 3*D
#define K_TOT 1024
#define RANK  5

// GEMM tiling
#define BM 128
#define BN 128
#define BK 32
#define STAGES 3
#define CHUNK_FLOATS 4096              // one 128x32 tile, packed
#define STAGE_BYTES 32768              // A tile 16KB + B tile 16KB
#define SMEM_BYTES (STAGES * STAGE_BYTES)   // 98304

// Operands in packed fragment-major layout, tf32-rounded.
// A chunks: (mblk in [0,256)) x (kt in [0,32)), 4096 floats each.
//   within chunk: offset = ((r16*4 + kk)*32 + lane)*4 + v
//     row = r16*16 + qr + 8*hi, k = kt*32 + kk*8 + qc + 4*khi,
//     lane = qr*4 + qc, v = hi + 2*khi
// B chunks: (nblk in [0,24)) x (kt in [0,32)), 4096 floats each.
//   within chunk: offset = (((r8*4 + kk)*32 + lane)*2 + khi)
//     n = r8*8 + qr, k = kt*32 + kk*8 + qc + 4*khi
__device__ float g_xr[(size_t)M_TOT * K_TOT];
__device__ float g_Wd[(size_t)N_TOT * K_TOT];

__device__ __forceinline__ float f2tf32f(float x) {
    uint32_t r;
    asm("cvt.rna.tf32.f32 %0, %1;" : "=r"(r) : "f"(x));
    return __uint_as_float(r);
}

// ---------------------------------------------------------------------------
// Combined prep: round+repack x, and round+repack (W + LoRA delta).
// 2 launches per kernel_launch call => ncu -s 5 profiles the GEMM.
// ---------------------------------------------------------------------------
__global__ void __launch_bounds__(256)
prep_all(const float* __restrict__ x, const float* __restrict__ W,
         const float* __restrict__ A0, const float* __restrict__ A1,
         const float* __restrict__ B0, const float* __restrict__ B1,
         const float* __restrict__ s0p, const float* __restrict__ s1p)
{
    const int b = blockIdx.x;
    const int tid = threadIdx.x;

    if (b < 8192) {
        // ---- x part: one 128x32 chunk per block ----
        const int mblk = b >> 5;
        const int kt   = b & 31;
        const float* xin = x + (size_t)mblk * 128 * K_TOT;
        float4* outp = reinterpret_cast<float4*>(g_xr) + (size_t)b * 1024;
#pragma unroll
        for (int s = 0; s < 4; s++) {
            const int slot = tid + s * 256;        // 0..1023
            const int lane = slot & 31;
            const int kk   = (slot >> 5) & 3;
            const int r16  = slot >> 7;            // 0..7
            const int qr = lane >> 2, qc = lane & 3;
            const int row0 = r16 * 16 + qr;
            const int k0   = kt * 32 + kk * 8 + qc;
            float4 v;
            v.x = f2tf32f(xin[(size_t)row0 * K_TOT + k0]);
            v.y = f2tf32f(xin[(size_t)(row0 + 8) * K_TOT + k0]);
            v.z = f2tf32f(xin[(size_t)row0 * K_TOT + k0 + 4]);
            v.w = f2tf32f(xin[(size_t)(row0 + 8) * K_TOT + k0 + 4]);
            outp[slot] = v;
        }
    } else {
        // ---- W part: one 128x32 chunk per block ----
        const int bb   = b - 8192;                 // 0..767
        const int nblk = bb >> 5;
        const int kt   = bb & 31;
        const float s0 = s0p[0], s1 = s1p[0];
        float2* outp = reinterpret_cast<float2*>(g_Wd) + (size_t)bb * 2048;
#pragma unroll
        for (int s = 0; s < 8; s++) {
            const int slot = tid + s * 256;        // 0..2047
            const int lane = slot & 31;
            const int kk   = (slot >> 5) & 3;
            const int r8   = slot >> 7;            // 0..15
            const int qr = lane >> 2, qc = lane & 3;
            const int n  = nblk * 128 + r8 * 8 + qr;
            const int k0 = kt * 32 + kk * 8 + qc;
            float w0 = W[(size_t)n * K_TOT + k0];
            float w1 = W[(size_t)n * K_TOT + k0 + 4];
            if (n >= D_DIM) {
                float d0 = 0.f, d1 = 0.f;
                if (n < 2 * D_DIM) {
                    const int r = n - D_DIM;
#pragma unroll
                    for (int j = 0; j < RANK; j++) {
                        const float bj = B0[r * RANK + j];
                        d0 += bj * A0[j * K_TOT + k0];
                        d1 += bj * A0[j * K_TOT + k0 + 4];
                    }
                    w0 += s0 * d0; w1 += s0 * d1;
                } else {
                    const int r = n - 2 * D_DIM;
#pragma unroll
                    for (int j = 0; j < RANK; j++) {
                        const float bj = B1[r * RANK + j];
                        d0 += bj * A1[j * K_TOT + k0];
                        d1 += bj * A1[j * K_TOT + k0 + 4];
                    }
                    w0 += s1 * d0; w1 += s1 * d1;
                }
            }
            outp[slot] = make_float2(f2tf32f(w0), f2tf32f(w1));
        }
    }
}

// ---------------------------------------------------------------------------
// TF32 GEMM on packed operands: C = A * Wd^T + bias
// ---------------------------------------------------------------------------
__global__ __launch_bounds__(256, 2)
void gemm_tf32(const float* __restrict__ bias,
               float* __restrict__ C)
{
    extern __shared__ char smem[];

    const int tid  = threadIdx.x;
    const int warp = tid >> 5;
    const int lane = tid & 31;
    const int wm = warp >> 2;       // 0..1
    const int wn = warp & 3;        // 0..3
    const int qr = lane >> 2;
    const int qc = lane & 3;

    const int nblk = blockIdx.x;    // 0..23
    const int mblk = blockIdx.y;    // 0..255

    const float* gA = g_xr + (size_t)mblk * 32 * CHUNK_FLOATS;
    const float* gB = g_Wd + (size_t)nblk * 32 * CHUNK_FLOATS;

    const uint32_t sbase = (uint32_t)__cvta_generic_to_shared(smem);

    float acc[4][4][4];
#pragma unroll
    for (int i = 0; i < 4; i++)
#pragma unroll
        for (int j = 0; j < 4; j++)
#pragma unroll
            for (int c = 0; c < 4; c++) acc[i][j][c] = 0.f;

    // Linear 16KB+16KB copy: thread writes 4x16B per matrix per stage.
    auto issue = [&](int kt) {
        const int st = kt % STAGES;
        const uint32_t sdst = sbase + (uint32_t)(st * STAGE_BYTES) + (uint32_t)(tid * 16);
        const float* asrc = gA + (size_t)kt * CHUNK_FLOATS + tid * 4;
        const float* bsrc = gB + (size_t)kt * CHUNK_FLOATS + tid * 4;
#pragma unroll
        for (int i = 0; i < 4; i++) {
            asm volatile("cp.async.cg.shared.global [%0], [%1], 16;"
                         :: "r"(sdst + (uint32_t)(i * 4096)), "l"(asrc + i * 1024));
            asm volatile("cp.async.cg.shared.global [%0], [%1], 16;"
                         :: "r"(sdst + 16384u + (uint32_t)(i * 4096)), "l"(bsrc + i * 1024));
        }
        asm volatile("cp.async.commit_group;");
    };

    constexpr int NT = K_TOT / BK;  // 32
    issue(0);
    issue(1);

    for (int kt = 0; kt < NT; kt++) {
        if (kt < NT - 1) asm volatile("cp.async.wait_group 1;");
        else             asm volatile("cp.async.wait_group 0;");
        __syncthreads();
        if (kt + 2 < NT) issue(kt + 2);   // writes stage (kt-1)%3: all readers sync'd above

        const char* stg = smem + (kt % STAGES) * STAGE_BYTES;

#pragma unroll
        for (int kk = 0; kk < 4; kk++) {
            uint4 af[4];
            uint2 bf[4];
#pragma unroll
            for (int mt = 0; mt < 4; mt++)
                af[mt] = *reinterpret_cast<const uint4*>(
                    stg + ((((wm * 4 + mt) * 4 + kk) * 32 + lane) << 4));
#pragma unroll
            for (int nt = 0; nt < 4; nt++)
                bf[nt] = *reinterpret_cast<const uint2*>(
                    stg + 16384 + ((((wn * 4 + nt) * 4 + kk) * 32 + lane) << 3));
#pragma unroll
            for (int mt = 0; mt < 4; mt++)
#pragma unroll
                for (int nt = 0; nt < 4; nt++) {
                    asm volatile(
                        "mma.sync.aligned.m16n8k8.row.col.f32.tf32.tf32.f32 "
                        "{%0,%1,%2,%3},{%4,%5,%6,%7},{%8,%9},{%0,%1,%2,%3};"
                        : "+f"(acc[mt][nt][0]), "+f"(acc[mt][nt][1]),
                          "+f"(acc[mt][nt][2]), "+f"(acc[mt][nt][3])
                        : "r"(af[mt].x), "r"(af[mt].y), "r"(af[mt].z), "r"(af[mt].w),
                          "r"(bf[nt].x), "r"(bf[nt].y));
                }
        }
    }

    // Epilogue: +bias, float2 stores
    const int m0 = mblk * BM;
    const int n0 = nblk * BN;
#pragma unroll
    for (int mt = 0; mt < 4; mt++) {
        const int row0 = m0 + wm * 64 + mt * 16 + qr;
#pragma unroll
        for (int nt = 0; nt < 4; nt++) {
            const int col0 = n0 + wn * 32 + nt * 8 + qc * 2;
            const float2 bv = *reinterpret_cast<const float2*>(&bias[col0]);
            float2 v0, v1;
            v0.x = acc[mt][nt][0] + bv.x;
            v0.y = acc[mt][nt][1] + bv.y;
            v1.x = acc[mt][nt][2] + bv.x;
            v1.y = acc[mt][nt][3] + bv.y;
            *reinterpret_cast<float2*>(&C[(size_t)row0 * N_TOT + col0])       = v0;
            *reinterpret_cast<float2*>(&C[(size_t)(row0 + 8) * N_TOT + col0]) = v1;
        }
    }
}

// ---------------------------------------------------------------------------
extern "C" void kernel_launch(void* const* d_in, const int* in_sizes, int n_in,
                              void* d_out, int out_size)
{
    const float* x    = (const float*)d_in[0];
    const float* W    = (const float*)d_in[1];
    const float* bias = (const float*)d_in[2];
    const float* A0   = (const float*)d_in[3];
    const float* A1   = (const float*)d_in[4];
    const float* B0   = (const float*)d_in[5];
    const float* B1   = (const float*)d_in[6];
    const float* s0   = (const float*)d_in[7];
    const float* s1   = (const float*)d_in[8];
    float* out = (float*)d_out;

    (void)in_sizes; (void)n_in; (void)out_size;

    // 1) Round + repack both operands (fragment-major layout).
    prep_all<<<8192 + 768, 256>>>(x, W, A0, A1, B0, B1, s0, s1);

    // 2) TF32 tensor-core GEMM, 3-stage cp.async pipeline, 2 CTAs/SM.
    cudaFuncSetAttribute(gemm_tf32, cudaFuncAttributeMaxDynamicSharedMemorySize,
                         SMEM_BYTES);
    dim3 grid(N_TOT / BN, M_TOT / BM);
    gemm_tf32<<<grid, 256, SMEM_BYTES>>>(bias, out);
}